// round 4
// baseline (speedup 1.0000x reference)
#include <cuda_runtime.h>
#include <math.h>

#define Bn   4
#define Cc   64
#define Hh   128
#define Ww   128
#define HW   (Hh*Ww)        // 16384
#define Nn   9
#define KTOT 576            // 64*9
#define M2   603            // 18 + 9 + 576 combined output channels
#define OUTC 64

// ---- scratch (static __device__, no allocation) ----
__device__ float g_fused[Bn*Cc*HW];            // 16.8 MB
__device__ float g_Wall[M2*KTOT];              // packed weights of the 3 convs
__device__ float g_Ball[M2];                   // packed biases
__device__ float g_off[Bn*18*HW];              // raw offsets
__device__ float g_m[Bn*Nn*HW];                // sigmoid mask
__device__ float g_coff[Bn*KTOT*HW];           // tanh color offsets (155 MB)

// ============================================================
// Kernel 0: pack the 3 conv weight tensors into one [603][576]
// ============================================================
__global__ void pack_kernel(const float* __restrict__ wp, const float* __restrict__ wm,
                            const float* __restrict__ wc, const float* __restrict__ bp,
                            const float* __restrict__ bm, const float* __restrict__ bc) {
    int i = blockIdx.x * blockDim.x + threadIdx.x;
    const int n1 = M2 * KTOT;
    if (i < n1) {
        int row = i / KTOT;
        float v;
        if (row < 18)      v = wp[i];
        else if (row < 27) v = wm[i - 18*KTOT];
        else               v = wc[i - 27*KTOT];
        g_Wall[i] = v;
    } else if (i < n1 + M2) {
        int row = i - n1;
        float v;
        if (row < 18)      v = bp[row];
        else if (row < 27) v = bm[row - 18];
        else               v = bc[row - 27];
        g_Ball[row] = v;
    }
}

// ============================================================
// Kernel 1: 1x1 conv on concat(x, ref) -> g_fused
// GEMM: M=64 (outc), K=128, N=pixels. Tile 64x64x16, 4x4/thread.
// ============================================================
__global__ __launch_bounds__(256) void conv1x1_kernel(
    const float* __restrict__ x, const float* __restrict__ ref,
    const float* __restrict__ w, const float* __restrict__ bias)
{
    __shared__ float As[16][64];
    __shared__ float Bs[16][64];
    int tid = threadIdx.x;
    int px0 = blockIdx.x * 64;
    int b   = px0 >> 14;
    int hw0 = px0 & (HW - 1);
    int tm0 = (tid >> 4) << 2;
    int tn0 = (tid & 15) << 2;
    float acc[4][4] = {};

    for (int k0 = 0; k0 < 128; k0 += 16) {
#pragma unroll
        for (int i = 0; i < 4; i++) {
            int e  = tid + 256 * i;
            int m  = e >> 4, kk = e & 15;
            As[kk][m] = w[m * 128 + k0 + kk];
            int kb = e >> 6, n = e & 63;
            int k  = k0 + kb;
            const float* src = (k < 64) ? x : ref;
            int kc = (k < 64) ? k : k - 64;
            Bs[kb][n] = src[((b * Cc + kc) << 14) + hw0 + n];
        }
        __syncthreads();
#pragma unroll
        for (int j = 0; j < 16; j++) {
            float4 a  = *(const float4*)&As[j][tm0];
            float4 bb = *(const float4*)&Bs[j][tn0];
            float av[4] = {a.x, a.y, a.z, a.w};
            float bv[4] = {bb.x, bb.y, bb.z, bb.w};
#pragma unroll
            for (int ii = 0; ii < 4; ii++)
#pragma unroll
                for (int jj = 0; jj < 4; jj++)
                    acc[ii][jj] += av[ii] * bv[jj];
        }
        __syncthreads();
    }
#pragma unroll
    for (int ii = 0; ii < 4; ii++) {
        float bi = bias[tm0 + ii];
#pragma unroll
        for (int jj = 0; jj < 4; jj++)
            g_fused[((b * Cc + tm0 + ii) << 14) + hw0 + tn0 + jj] = acc[ii][jj] + bi;
    }
}

// ============================================================
// Kernel 2: combined 3x3 conv (implicit GEMM), M=603, K=576, N=pixels.
// Epilogue: rows [0,18) raw -> g_off, [18,27) sigmoid -> g_m,
//           [27,603) tanh -> g_coff.
// ============================================================
__global__ __launch_bounds__(256) void conv3x3_kernel()
{
    __shared__ float As[16][64];
    __shared__ float Bs[16][64];
    int tid = threadIdx.x;
    int px0 = blockIdx.x * 64;
    int b   = px0 >> 14;
    int rem = px0 & (HW - 1);
    int y   = rem >> 7;
    int x0  = rem & 127;          // 0 or 64
    int m0  = blockIdx.y * 64;
    int tm0 = (tid >> 4) << 2;
    int tn0 = (tid & 15) << 2;
    float acc[4][4] = {};

    for (int k0 = 0; k0 < KTOT; k0 += 16) {
#pragma unroll
        for (int i = 0; i < 4; i++) {
            int e  = tid + 256 * i;
            int m  = e >> 4, kk = e & 15;
            int row = m0 + m;
            As[kk][m] = (row < M2) ? g_Wall[row * KTOT + k0 + kk] : 0.f;

            int kb = e >> 6, n = e & 63;
            int k  = k0 + kb;
            int ci = k / 9;
            int tap = k - ci * 9;
            int dy = tap / 3 - 1;
            int dx = tap - (tap / 3) * 3 - 1;
            int yy = y + dy, xx = x0 + n + dx;
            float v = 0.f;
            if ((unsigned)yy < 128u && (unsigned)xx < 128u)
                v = g_fused[((b * Cc + ci) << 14) + (yy << 7) + xx];
            Bs[kb][n] = v;
        }
        __syncthreads();
#pragma unroll
        for (int j = 0; j < 16; j++) {
            float4 a  = *(const float4*)&As[j][tm0];
            float4 bb = *(const float4*)&Bs[j][tn0];
            float av[4] = {a.x, a.y, a.z, a.w};
            float bv[4] = {bb.x, bb.y, bb.z, bb.w};
#pragma unroll
            for (int ii = 0; ii < 4; ii++)
#pragma unroll
                for (int jj = 0; jj < 4; jj++)
                    acc[ii][jj] += av[ii] * bv[jj];
        }
        __syncthreads();
    }

    int hwbase = (y << 7) + x0 + tn0;
#pragma unroll
    for (int ii = 0; ii < 4; ii++) {
        int row = m0 + tm0 + ii;
        if (row >= M2) continue;
        float bi = g_Ball[row];
#pragma unroll
        for (int jj = 0; jj < 4; jj++) {
            float v = acc[ii][jj] + bi;
            int hw = hwbase + jj;
            if (row < 18)
                g_off[((b * 18 + row) << 14) + hw] = v;
            else if (row < 27)
                g_m[((b * 9 + (row - 18)) << 14) + hw] = 1.f / (1.f + expf(-v));
            else
                g_coff[((b * KTOT + (row - 27)) << 14) + hw] = tanhf(v);
        }
    }
}

// ============================================================
// Kernel 3: deformable bilinear sampling + c_off + mask + final conv.
// One block = 16 pixels. v[c*9+n] built in smem, then per-pixel
// GEMM out[64] = Wconv[64,576] * v[576].
// ============================================================
__global__ __launch_bounds__(256) void sample_final_kernel(
    const float* __restrict__ x, const float* __restrict__ wconv,
    float* __restrict__ out)
{
    __shared__ float v_s[16][577];
    __shared__ int   idx_s[16][9][4];
    __shared__ float g_s[16][9][4];
    __shared__ float m_s[16][9];
    __shared__ float Ws[16][64];

    int tid = threadIdx.x;
    int px0 = blockIdx.x * 16;
    int b   = px0 >> 14;
    int rem = px0 & (HW - 1);
    int y   = rem >> 7;
    int x0  = rem & 127;

    // ---- phase 0: offsets -> sample coords, weights, mask ----
    if (tid < 144) {
        int px = tid / 9, n = tid - (tid / 9) * 9;
        int xg = x0 + px;
        int hw = (y << 7) + xg;
        float offr = g_off[((b * 18 + n) << 14) + hw];
        float offc = g_off[((b * 18 + 9 + n) << 14) + hw];
        m_s[px][n] = g_m[((b * 9 + n) << 14) + hw];

        float pr = (float)(y + 1 + (n / 3) - 1) + offr;   // padded-grid row
        float pc = (float)(xg + 1 + (n % 3) - 1) + offc;  // padded-grid col
        float fr = floorf(pr), fc = floorf(pc);
        int lt_r = min(max((int)fr, 0), 129);
        int rb_r = min(max((int)fr + 1, 0), 129);
        int lt_c = min(max((int)fc, 0), 129);
        int rb_c = min(max((int)fc + 1, 0), 129);
        float prc = fminf(fmaxf(pr, 0.f), 129.f);
        float pcc = fminf(fmaxf(pc, 0.f), 129.f);
        float ar_lt = 1.f + (float)lt_r - prc;
        float ar_rb = 1.f - ((float)rb_r - prc);
        float ac_lt = 1.f + (float)lt_c - pcc;
        float ac_rb = 1.f - ((float)rb_c - pcc);
        g_s[px][n][0] = ar_lt * ac_lt;   // lt
        g_s[px][n][1] = ar_rb * ac_rb;   // rb
        g_s[px][n][2] = ar_lt * ac_rb;   // lb (lt row, rb col)
        g_s[px][n][3] = ar_rb * ac_lt;   // rt (rb row, lt col)
        // unpadded image indices (pad=1), -1 => zero sample
        int rl = lt_r - 1, cl = lt_c - 1, rr = rb_r - 1, cr = rb_c - 1;
        idx_s[px][n][0] = ((unsigned)rl < 128u && (unsigned)cl < 128u) ? (rl << 7) + cl : -1;
        idx_s[px][n][1] = ((unsigned)rr < 128u && (unsigned)cr < 128u) ? (rr << 7) + cr : -1;
        idx_s[px][n][2] = ((unsigned)rl < 128u && (unsigned)cr < 128u) ? (rl << 7) + cr : -1;
        idx_s[px][n][3] = ((unsigned)rr < 128u && (unsigned)cl < 128u) ? (rr << 7) + cl : -1;
    }
    __syncthreads();

    // ---- phase 1: build v[px][c*9+n] ----
    {
        int px = tid & 15;
        int cg = tid >> 4;                 // 0..15, 4 channels each
        int xg = x0 + px;
        int hw = (y << 7) + xg;
#pragma unroll
        for (int n = 0; n < 9; n++) {
            int i0 = idx_s[px][n][0], i1 = idx_s[px][n][1];
            int i2 = idx_s[px][n][2], i3 = idx_s[px][n][3];
            float w0 = g_s[px][n][0], w1 = g_s[px][n][1];
            float w2 = g_s[px][n][2], w3 = g_s[px][n][3];
            float mm = m_s[px][n];
#pragma unroll
            for (int cc = 0; cc < 4; cc++) {
                int c = cg * 4 + cc;
                const float* xb = x + ((b * Cc + c) << 14);
                float s = 0.f;
                if (i0 >= 0) s += w0 * xb[i0];
                if (i1 >= 0) s += w1 * xb[i1];
                if (i2 >= 0) s += w2 * xb[i2];
                if (i3 >= 0) s += w3 * xb[i3];
                float coff = g_coff[((b * KTOT + c * 9 + n) << 14) + hw];
                v_s[px][c * 9 + n] = (s + coff) * mm;
            }
        }
    }

    // ---- phase 2: out[oc][px] = Wconv[oc][:] . v[px][:] ----
    int px  = tid & 15;
    int oc0 = (tid >> 4) << 2;
    float acc[4] = {};
    for (int k0 = 0; k0 < KTOT; k0 += 16) {
        __syncthreads();
#pragma unroll
        for (int i = 0; i < 4; i++) {
            int e  = tid + 256 * i;
            int kk = e >> 6, oc = e & 63;
            Ws[kk][oc] = wconv[oc * KTOT + k0 + kk];
        }
        __syncthreads();
#pragma unroll
        for (int kk = 0; kk < 16; kk++) {
            float bv = v_s[px][k0 + kk];
            float4 wv = *(const float4*)&Ws[kk][oc0];
            acc[0] += wv.x * bv;
            acc[1] += wv.y * bv;
            acc[2] += wv.z * bv;
            acc[3] += wv.w * bv;
        }
    }
    int xg = x0 + px;
    int hw = (y << 7) + xg;
#pragma unroll
    for (int i = 0; i < 4; i++)
        out[((b * OUTC + oc0 + i) << 14) + hw] = acc[i];
}

// ============================================================
extern "C" void kernel_launch(void* const* d_in, const int* in_sizes, int n_in,
                              void* d_out, int out_size)
{
    const float* x      = (const float*)d_in[0];
    const float* ref    = (const float*)d_in[1];
    const float* w_cd   = (const float*)d_in[2];
    const float* b_cd   = (const float*)d_in[3];
    const float* w_p    = (const float*)d_in[4];
    const float* b_p    = (const float*)d_in[5];
    const float* w_m    = (const float*)d_in[6];
    const float* b_m    = (const float*)d_in[7];
    const float* w_c    = (const float*)d_in[8];
    const float* b_c    = (const float*)d_in[9];
    const float* w_conv = (const float*)d_in[10];
    float* out = (float*)d_out;

    int packN = M2 * KTOT + M2;
    pack_kernel<<<(packN + 255) / 256, 256>>>(w_p, w_m, w_c, b_p, b_m, b_c);

    conv1x1_kernel<<<(Bn * HW) / 64, 256>>>(x, ref, w_cd, b_cd);

    dim3 g2((Bn * HW) / 64, (M2 + 63) / 64);
    conv3x3_kernel<<<g2, 256>>>();

    sample_final_kernel<<<(Bn * HW) / 16, 256>>>(x, w_conv, out);
}

// round 7
// speedup vs baseline: 1.3632x; 1.3632x over previous
#include <cuda_runtime.h>
#include <math.h>

#define Bn   4
#define Cc   64
#define Hh   128
#define Ww   128
#define HW   (Hh*Ww)        // 16384
#define Nn   9
#define KTOT 576            // 64*9
#define M2   603            // 18 + 9 + 576 combined output channels
#define OUTC 64

// ---- scratch (static __device__, no allocation) ----
__device__ float g_fused[Bn*Cc*HW];            // 16.8 MB
__device__ float g_Wall[M2*KTOT];              // packed weights of the 3 convs
__device__ float g_Ball[M2];                   // packed biases
__device__ float g_wt[KTOT*OUTC];              // w_conv transposed [k][oc]
__device__ float g_off[Bn*18*HW];              // raw offsets
__device__ float g_m[Bn*Nn*HW];                // sigmoid mask
__device__ float g_cofft[Bn*HW*KTOT];          // tanh color offsets, [b][hw][n*64+c]
__device__ float g_xt[Bn*HW*Cc];               // x transposed [b][hw][c]

// ============================================================
// Kernel 0: pack weights/biases + transpose w_conv
// ============================================================
__global__ void pack_kernel(const float* __restrict__ wp, const float* __restrict__ wm,
                            const float* __restrict__ wc, const float* __restrict__ bp,
                            const float* __restrict__ bm, const float* __restrict__ bc,
                            const float* __restrict__ wconv) {
    int i = blockIdx.x * blockDim.x + threadIdx.x;
    const int n1 = M2 * KTOT;
    const int n2 = n1 + M2;
    if (i < n1) {
        int row = i / KTOT;
        float v;
        if (row < 18)      v = wp[i];
        else if (row < 27) v = wm[i - 18*KTOT];
        else               v = wc[i - 27*KTOT];
        g_Wall[i] = v;
    } else if (i < n2) {
        int row = i - n1;
        float v;
        if (row < 18)      v = bp[row];
        else if (row < 27) v = bm[row - 18];
        else               v = bc[row - 27];
        g_Ball[row] = v;
    } else if (i < n2 + OUTC * KTOT) {
        int i2 = i - n2;
        int oc = i2 / KTOT;
        int k  = i2 - oc * KTOT;
        g_wt[k * OUTC + oc] = wconv[i2];
    }
}

// ============================================================
// Kernel 0b: transpose x -> x_t[b][hw][c]
// ============================================================
__global__ __launch_bounds__(256) void transpose_kernel(const float* __restrict__ x)
{
    __shared__ float t[32][33];
    int hw0 = blockIdx.x * 32;
    int c0  = blockIdx.y * 32;
    int b   = blockIdx.z;
    int tx = threadIdx.x, ty = threadIdx.y;
#pragma unroll
    for (int i = 0; i < 32; i += 8)
        t[ty + i][tx] = x[((b * Cc + c0 + ty + i) << 14) + hw0 + tx];
    __syncthreads();
#pragma unroll
    for (int i = 0; i < 32; i += 8)
        g_xt[((b * HW + hw0 + ty + i) << 6) + c0 + tx] = t[tx][ty + i];
}

// ============================================================
// Kernel 1: 1x1 conv on concat(x, ref) -> g_fused
// ============================================================
__global__ __launch_bounds__(256) void conv1x1_kernel(
    const float* __restrict__ x, const float* __restrict__ ref,
    const float* __restrict__ w, const float* __restrict__ bias)
{
    __shared__ float As[16][64];
    __shared__ float Bs[16][64];
    int tid = threadIdx.x;
    int px0 = blockIdx.x * 64;
    int b   = px0 >> 14;
    int hw0 = px0 & (HW - 1);
    int tm0 = (tid >> 4) << 2;
    int tn0 = (tid & 15) << 2;
    float acc[4][4] = {};

    for (int k0 = 0; k0 < 128; k0 += 16) {
#pragma unroll
        for (int i = 0; i < 4; i++) {
            int e  = tid + 256 * i;
            int m  = e >> 4, kk = e & 15;
            As[kk][m] = w[m * 128 + k0 + kk];
            int kb = e >> 6, n = e & 63;
            int k  = k0 + kb;
            const float* src = (k < 64) ? x : ref;
            int kc = (k < 64) ? k : k - 64;
            Bs[kb][n] = src[((b * Cc + kc) << 14) + hw0 + n];
        }
        __syncthreads();
#pragma unroll
        for (int j = 0; j < 16; j++) {
            float4 a  = *(const float4*)&As[j][tm0];
            float4 bb = *(const float4*)&Bs[j][tn0];
            float av[4] = {a.x, a.y, a.z, a.w};
            float bv[4] = {bb.x, bb.y, bb.z, bb.w};
#pragma unroll
            for (int ii = 0; ii < 4; ii++)
#pragma unroll
                for (int jj = 0; jj < 4; jj++)
                    acc[ii][jj] += av[ii] * bv[jj];
        }
        __syncthreads();
    }
#pragma unroll
    for (int ii = 0; ii < 4; ii++) {
        float bi = bias[tm0 + ii];
#pragma unroll
        for (int jj = 0; jj < 4; jj++)
            g_fused[((b * Cc + tm0 + ii) << 14) + hw0 + tn0 + jj] = acc[ii][jj] + bi;
    }
}

// ============================================================
// Kernel 2: combined 3x3 conv (implicit GEMM), M=603->640, K=576,
// N tile = 128 px (one full image row). 128x128 tile, 8x8/thread
// (split 4+4 at +64). Epilogue routes rows to off/mask/cofft.
// ============================================================
__global__ __launch_bounds__(256, 2) void conv3x3_kernel()
{
    __shared__ float As[8][128];
    __shared__ float Bs[8][128];
    int tid = threadIdx.x;
    int px0 = blockIdx.x * 128;
    int b   = px0 >> 14;
    int y   = (px0 & (HW - 1)) >> 7;
    int m0  = blockIdx.y * 128;
    int tn0 = (tid & 15) << 2;
    int tm0 = (tid >> 4) << 2;
    float acc[8][8] = {};

    for (int k0 = 0; k0 < KTOT; k0 += 8) {
        // load A: 8 k x 128 rows  (1024 elems, 4 passes of 256)
#pragma unroll
        for (int i = 0; i < 4; i++) {
            int e  = tid + 256 * i;
            int kk = e & 7, m = e >> 3;
            int row = m0 + m;
            As[kk][m] = (row < M2) ? g_Wall[row * KTOT + k0 + kk] : 0.f;
        }
        // load B: 8 k x 128 px (1024 elems, 4 passes of 256) — im2col of g_fused
#pragma unroll
        for (int i = 0; i < 4; i++) {
            int e  = tid + 256 * i;
            int kb = e >> 7, n = e & 127;
            int k  = k0 + kb;
            int ci = k / 9;
            int tap = k - ci * 9;
            int dy = tap / 3 - 1;
            int dx = tap - (tap / 3) * 3 - 1;
            int yy = y + dy, xx = n + dx;
            float v = 0.f;
            if ((unsigned)yy < 128u && (unsigned)xx < 128u)
                v = g_fused[((b * Cc + ci) << 14) + (yy << 7) + xx];
            Bs[kb][n] = v;
        }
        __syncthreads();
#pragma unroll
        for (int j = 0; j < 8; j++) {
            float a[8], bb[8];
            *(float4*)&a[0]  = *(const float4*)&As[j][tm0];
            *(float4*)&a[4]  = *(const float4*)&As[j][tm0 + 64];
            *(float4*)&bb[0] = *(const float4*)&Bs[j][tn0];
            *(float4*)&bb[4] = *(const float4*)&Bs[j][tn0 + 64];
#pragma unroll
            for (int ii = 0; ii < 8; ii++)
#pragma unroll
                for (int jj = 0; jj < 8; jj++)
                    acc[ii][jj] += a[ii] * bb[jj];
        }
        __syncthreads();
    }

    int hwb = (y << 7);
    int bhw = b * HW;
#pragma unroll
    for (int ii2 = 0; ii2 < 2; ii2++)
#pragma unroll
    for (int ii = 0; ii < 4; ii++) {
        int row = m0 + tm0 + ii2 * 64 + ii;
        if (row >= M2) continue;
        float bi = g_Ball[row];
#pragma unroll
        for (int jj2 = 0; jj2 < 2; jj2++)
#pragma unroll
        for (int jj = 0; jj < 4; jj++) {
            float v = acc[ii2 * 4 + ii][jj2 * 4 + jj] + bi;
            int hw = hwb + tn0 + jj2 * 64 + jj;
            if (row < 18)
                g_off[((b * 18 + row) << 14) + hw] = v;
            else if (row < 27)
                g_m[((b * 9 + (row - 18)) << 14) + hw] = 1.f / (1.f + expf(-v));
            else {
                int t = row - 27;
                int cch = t / 9;
                int nn  = t - cch * 9;
                g_cofft[(size_t)(bhw + hw) * KTOT + nn * 64 + cch] = tanhf(v);
            }
        }
    }
}

// ============================================================
// Kernel 3: deformable bilinear sampling + c_off + mask + final conv.
// Block = 16 pixels, 256 threads. All gathers coalesced along channels
// via x_t / g_cofft / g_wt layouts.
// ============================================================
__global__ __launch_bounds__(256) void sample_final_kernel(float* __restrict__ out)
{
    __shared__ float v_s[16][577];
    __shared__ int   idx_s[16][9][4];
    __shared__ float g_s[16][9][4];
    __shared__ float m_s[16][9];
    __shared__ float Ws[16][64];

    int tid = threadIdx.x;
    int px0 = blockIdx.x * 16;
    int b   = px0 >> 14;
    int rem = px0 & (HW - 1);
    int y   = rem >> 7;
    int x0  = rem & 127;

    // ---- phase 0: offsets -> sample coords, weights, mask ----
    if (tid < 144) {
        int px = tid / 9, n = tid - (tid / 9) * 9;
        int xg = x0 + px;
        int hw = (y << 7) + xg;
        float offr = g_off[((b * 18 + n) << 14) + hw];
        float offc = g_off[((b * 18 + 9 + n) << 14) + hw];
        m_s[px][n] = g_m[((b * 9 + n) << 14) + hw];

        float pr = (float)(y + 1 + (n / 3) - 1) + offr;   // padded-grid row
        float pc = (float)(xg + 1 + (n % 3) - 1) + offc;  // padded-grid col
        float fr = floorf(pr), fc = floorf(pc);
        int lt_r = min(max((int)fr, 0), 129);
        int rb_r = min(max((int)fr + 1, 0), 129);
        int lt_c = min(max((int)fc, 0), 129);
        int rb_c = min(max((int)fc + 1, 0), 129);
        float prc = fminf(fmaxf(pr, 0.f), 129.f);
        float pcc = fminf(fmaxf(pc, 0.f), 129.f);
        float ar_lt = 1.f + (float)lt_r - prc;
        float ar_rb = 1.f - ((float)rb_r - prc);
        float ac_lt = 1.f + (float)lt_c - pcc;
        float ac_rb = 1.f - ((float)rb_c - pcc);
        g_s[px][n][0] = ar_lt * ac_lt;   // lt
        g_s[px][n][1] = ar_rb * ac_rb;   // rb
        g_s[px][n][2] = ar_lt * ac_rb;   // lb
        g_s[px][n][3] = ar_rb * ac_lt;   // rt
        int rl = lt_r - 1, cl = lt_c - 1, rr = rb_r - 1, cr = rb_c - 1;
        idx_s[px][n][0] = ((unsigned)rl < 128u && (unsigned)cl < 128u) ? (rl << 7) + cl : -1;
        idx_s[px][n][1] = ((unsigned)rr < 128u && (unsigned)cr < 128u) ? (rr << 7) + cr : -1;
        idx_s[px][n][2] = ((unsigned)rl < 128u && (unsigned)cr < 128u) ? (rl << 7) + cr : -1;
        idx_s[px][n][3] = ((unsigned)rr < 128u && (unsigned)cl < 128u) ? (rr << 7) + cl : -1;
    }
    __syncthreads();

    // ---- phase 1: build v[px][c*9+n], coalesced in c ----
    {
        int c = tid & 63;
        const float* xtb = g_xt + ((b * HW) << 6);
#pragma unroll
        for (int p = 0; p < 4; p++) {
            int px = (tid >> 6) * 4 + p;
            int hw = (y << 7) + x0 + px;
            const float* cofft = g_cofft + (size_t)(b * HW + hw) * KTOT;
#pragma unroll
            for (int n = 0; n < 9; n++) {
                int i0 = idx_s[px][n][0], i1 = idx_s[px][n][1];
                int i2 = idx_s[px][n][2], i3 = idx_s[px][n][3];
                float w0 = g_s[px][n][0], w1 = g_s[px][n][1];
                float w2 = g_s[px][n][2], w3 = g_s[px][n][3];
                float mm = m_s[px][n];
                float s = 0.f;
                if (i0 >= 0) s += w0 * xtb[(i0 << 6) + c];
                if (i1 >= 0) s += w1 * xtb[(i1 << 6) + c];
                if (i2 >= 0) s += w2 * xtb[(i2 << 6) + c];
                if (i3 >= 0) s += w3 * xtb[(i3 << 6) + c];
                float coff = cofft[n * 64 + c];
                v_s[px][c * 9 + n] = (s + coff) * mm;
            }
        }
    }
    __syncthreads();

    // ---- phase 2: out[oc][px] = Wconv[oc][:] . v[px][:] ----
    int px  = tid & 15;
    int oc0 = (tid >> 4) << 2;
    float acc[4] = {};
    for (int k0 = 0; k0 < KTOT; k0 += 16) {
#pragma unroll
        for (int i = 0; i < 4; i++) {
            int e  = tid + 256 * i;
            int kk = e >> 6, oc = e & 63;
            Ws[kk][oc] = g_wt[(k0 + kk) * 64 + oc];
        }
        __syncthreads();
#pragma unroll
        for (int kk = 0; kk < 16; kk++) {
            float bv = v_s[px][k0 + kk];
            float4 wv = *(const float4*)&Ws[kk][oc0];
            acc[0] += wv.x * bv;
            acc[1] += wv.y * bv;
            acc[2] += wv.z * bv;
            acc[3] += wv.w * bv;
        }
        __syncthreads();
    }
    int hw = (y << 7) + x0 + px;
#pragma unroll
    for (int i = 0; i < 4; i++)
        out[((b * OUTC + oc0 + i) << 14) + hw] = acc[i];
}

// ============================================================
extern "C" void kernel_launch(void* const* d_in, const int* in_sizes, int n_in,
                              void* d_out, int out_size)
{
    const float* x      = (const float*)d_in[0];
    const float* ref    = (const float*)d_in[1];
    const float* w_cd   = (const float*)d_in[2];
    const float* b_cd   = (const float*)d_in[3];
    const float* w_p    = (const float*)d_in[4];
    const float* b_p    = (const float*)d_in[5];
    const float* w_m    = (const float*)d_in[6];
    const float* b_m    = (const float*)d_in[7];
    const float* w_c    = (const float*)d_in[8];
    const float* b_c    = (const float*)d_in[9];
    const float* w_conv = (const float*)d_in[10];
    float* out = (float*)d_out;

    int packN = M2 * KTOT + M2 + OUTC * KTOT;
    pack_kernel<<<(packN + 255) / 256, 256>>>(w_p, w_m, w_c, b_p, b_m, b_c, w_conv);

    dim3 gt(HW / 32, Cc / 32, Bn);
    transpose_kernel<<<gt, dim3(32, 8)>>>(x);

    conv1x1_kernel<<<(Bn * HW) / 64, 256>>>(x, ref, w_cd, b_cd);

    dim3 g2((Bn * HW) / 128, (M2 + 127) / 128);
    conv3x3_kernel<<<g2, 256>>>();

    sample_final_kernel<<<(Bn * HW) / 16, 256>>>(out);
}

// round 9
// speedup vs baseline: 1.5435x; 1.1323x over previous
#include <cuda_runtime.h>
#include <cuda_bf16.h>
#include <math.h>
#include <stdint.h>

#define Bn   4
#define Cc   64
#define HW   16384
#define KTOT 576
#define M2   603
#define OUTC 64

// ---- scratch (static __device__, no allocation) ----
__device__ float g_fused[Bn*Cc*HW];            // 16.8 MB
__device__ float g_Wall[M2*KTOT];              // packed weights of the 3 convs
__device__ float g_Ball[M2];                   // packed biases
__device__ float g_wt[KTOT*OUTC];              // w_conv transposed [k][oc]
__device__ float g_off[Bn*18*HW];              // raw offsets
__device__ float g_m[Bn*9*HW];                 // sigmoid mask
__device__ float g_cofft[(size_t)Bn*HW*KTOT];  // tanh color offsets, [b][hw][n*64+c]
__device__ float g_xt[Bn*HW*Cc];               // x transposed [b][hw][c]

// ============================================================
// Fast FFMA-only transcendentals (no MUFU)
// ============================================================
__device__ __forceinline__ float fast_exp2(float y) {
    y = fminf(fmaxf(y, -125.f), 125.f);
    float nb = y + 12582912.0f;                   // 1.5*2^23 round trick
    int   ni = __float_as_int(nb) - 0x4B400000;   // (int)rint(y)
    float f  = y - (nb - 12582912.0f);            // f in [-0.5, 0.5]
    float p = 1.5403530e-4f;
    p = fmaf(p, f, 1.3333558e-3f);
    p = fmaf(p, f, 9.6181291e-3f);
    p = fmaf(p, f, 5.5504109e-2f);
    p = fmaf(p, f, 2.4022651e-1f);
    p = fmaf(p, f, 6.9314718e-1f);
    p = fmaf(p, f, 1.0f);
    return p * __int_as_float((ni + 127) << 23);
}
__device__ __forceinline__ float fast_rcp(float u) {
    float r = __int_as_float(0x7EF311C3 - __float_as_int(u));
    r = r * (2.0f - u * r);
    r = r * (2.0f - u * r);
    r = r * (2.0f - u * r);
    return r;
}
__device__ __forceinline__ float fast_tanh(float x) {
    float t = fast_exp2(2.885390082f * x);        // e^{2x}
    return 1.0f - 2.0f * fast_rcp(1.0f + t);
}
__device__ __forceinline__ float fast_sigmoid(float x) {
    float t = fast_exp2(-1.442695041f * x);       // e^{-x}
    return fast_rcp(1.0f + t);
}

// ============================================================
// PROBE (never launched): does legacy mma.sync compile at target sm_103?
// If this compiles, Round 9 moves the 45.5-GFLOP GEMM to HMMA
// split-precision. It is deliberately NOT called from kernel_launch.
// ============================================================
__global__ void probe_mma_kernel(float* __restrict__ out,
                                 const __nv_bfloat16* __restrict__ a,
                                 const __nv_bfloat16* __restrict__ b)
{
    int t = threadIdx.x & 31;
    const uint32_t* ap = (const uint32_t*)a;
    const uint32_t* bp = (const uint32_t*)b;
    uint32_t ar0 = ap[t], ar1 = ap[t + 32], ar2 = ap[t + 64], ar3 = ap[t + 96];
    uint32_t br0 = bp[t], br1 = bp[t + 32];
    float d0 = 0.f, d1 = 0.f, d2 = 0.f, d3 = 0.f;
    asm volatile(
        "mma.sync.aligned.m16n8k16.row.col.f32.bf16.bf16.f32 "
        "{%0,%1,%2,%3}, {%4,%5,%6,%7}, {%8,%9}, {%0,%1,%2,%3};"
        : "+f"(d0), "+f"(d1), "+f"(d2), "+f"(d3)
        : "r"(ar0), "r"(ar1), "r"(ar2), "r"(ar3), "r"(br0), "r"(br1));
    // tf32 variant probe
    asm volatile(
        "mma.sync.aligned.m16n8k8.row.col.f32.tf32.tf32.f32 "
        "{%0,%1,%2,%3}, {%4,%5,%6,%7}, {%8,%9}, {%0,%1,%2,%3};"
        : "+f"(d0), "+f"(d1), "+f"(d2), "+f"(d3)
        : "r"(ar0), "r"(ar1), "r"(ar2), "r"(ar3), "r"(br0), "r"(br1));
    out[t] = d0 + d1 + d2 + d3;
}

// ============================================================
// Kernel 0: pack weights/biases + transpose w_conv
// ============================================================
__global__ void pack_kernel(const float* __restrict__ wp, const float* __restrict__ wm,
                            const float* __restrict__ wc, const float* __restrict__ bp,
                            const float* __restrict__ bm, const float* __restrict__ bc,
                            const float* __restrict__ wconv) {
    int i = blockIdx.x * blockDim.x + threadIdx.x;
    const int n1 = M2 * KTOT;
    const int n2 = n1 + M2;
    if (i < n1) {
        int row = i / KTOT;
        float v;
        if (row < 18)      v = wp[i];
        else if (row < 27) v = wm[i - 18*KTOT];
        else               v = wc[i - 27*KTOT];
        g_Wall[i] = v;
    } else if (i < n2) {
        int row = i - n1;
        float v;
        if (row < 18)      v = bp[row];
        else if (row < 27) v = bm[row - 18];
        else               v = bc[row - 27];
        g_Ball[row] = v;
    } else if (i < n2 + OUTC * KTOT) {
        int i2 = i - n2;
        int oc = i2 / KTOT;
        int k  = i2 - oc * KTOT;
        g_wt[k * OUTC + oc] = wconv[i2];
    }
}

// ============================================================
// Kernel 0b: transpose x -> x_t[b][hw][c]
// ============================================================
__global__ __launch_bounds__(256) void transpose_kernel(const float* __restrict__ x)
{
    __shared__ float t[32][33];
    int hw0 = blockIdx.x * 32;
    int c0  = blockIdx.y * 32;
    int b   = blockIdx.z;
    int tx = threadIdx.x, ty = threadIdx.y;
#pragma unroll
    for (int i = 0; i < 32; i += 8)
        t[ty + i][tx] = x[((b * Cc + c0 + ty + i) << 14) + hw0 + tx];
    __syncthreads();
#pragma unroll
    for (int i = 0; i < 32; i += 8)
        g_xt[((b * HW + hw0 + ty + i) << 6) + c0 + tx] = t[tx][ty + i];
}

// ============================================================
// Kernel 1: 1x1 conv on concat(x, ref) -> g_fused
// ============================================================
__global__ __launch_bounds__(256) void conv1x1_kernel(
    const float* __restrict__ x, const float* __restrict__ ref,
    const float* __restrict__ w, const float* __restrict__ bias)
{
    __shared__ float As[16][64];
    __shared__ float Bs[16][64];
    int tid = threadIdx.x;
    int px0 = blockIdx.x * 64;
    int b   = px0 >> 14;
    int hw0 = px0 & (HW - 1);
    int tm0 = (tid >> 4) << 2;
    int tn0 = (tid & 15) << 2;
    float acc[4][4] = {};

    for (int k0 = 0; k0 < 128; k0 += 16) {
#pragma unroll
        for (int i = 0; i < 4; i++) {
            int e  = tid + 256 * i;
            int m  = e >> 4, kk = e & 15;
            As[kk][m] = w[m * 128 + k0 + kk];
            int kb = e >> 6, n = e & 63;
            int k  = k0 + kb;
            const float* src = (k < 64) ? x : ref;
            int kc = (k < 64) ? k : k - 64;
            Bs[kb][n] = src[((b * Cc + kc) << 14) + hw0 + n];
        }
        __syncthreads();
#pragma unroll
        for (int j = 0; j < 16; j++) {
            float4 a  = *(const float4*)&As[j][tm0];
            float4 bb = *(const float4*)&Bs[j][tn0];
            float av[4] = {a.x, a.y, a.z, a.w};
            float bv[4] = {bb.x, bb.y, bb.z, bb.w};
#pragma unroll
            for (int ii = 0; ii < 4; ii++)
#pragma unroll
                for (int jj = 0; jj < 4; jj++)
                    acc[ii][jj] += av[ii] * bv[jj];
        }
        __syncthreads();
    }
#pragma unroll
    for (int ii = 0; ii < 4; ii++) {
        float bi = bias[tm0 + ii];
#pragma unroll
        for (int jj = 0; jj < 4; jj++)
            g_fused[((b * Cc + tm0 + ii) << 14) + hw0 + tn0 + jj] = acc[ii][jj] + bi;
    }
}

// ============================================================
// Kernel 2: combined 3x3 conv (implicit GEMM), M=603->640, K=576,
// N tile = 128 px. 128x128 tile, 8x8/thread, DOUBLE-BUFFERED smem
// (one __syncthreads per K-chunk, prefetch overlaps compute).
// Epilogue: FFMA-only sigmoid/tanh (no MUFU).
// ============================================================
__global__ __launch_bounds__(256, 2) void conv3x3_kernel()
{
    __shared__ float As[2][8][128];
    __shared__ float Bs[2][8][128];
    int tid = threadIdx.x;
    int px0 = blockIdx.x * 128;
    int b   = px0 >> 14;
    int y   = (px0 & (HW - 1)) >> 7;
    int m0  = blockIdx.y * 128;
    int tn0 = (tid & 15) << 2;
    int tm0 = (tid >> 4) << 2;
    float acc[8][8] = {};

    // per-thread loader coords (fixed)
    int a_kk = tid & 7;           // A: k within chunk
    int a_m  = tid >> 3;          // A: row base (+32*i)
    int b_n  = tid & 127;         // B: pixel
    int b_kb = tid >> 7;          // B: k within chunk base (+2*i)

    const int NCH = KTOT / 8;     // 72 chunks

    // ---- prologue: load chunk 0 into buffer 0 ----
    {
#pragma unroll
        for (int i = 0; i < 4; i++) {
            int m = a_m + 32 * i;
            int row = m0 + m;
            As[0][a_kk][m] = (row < M2) ? g_Wall[row * KTOT + a_kk] : 0.f;
        }
#pragma unroll
        for (int i = 0; i < 4; i++) {
            int kb = b_kb + 2 * i;
            int k  = kb;
            int ci = k / 9;
            int tap = k - ci * 9;
            int dy = tap / 3 - 1;
            int dx = tap - (tap / 3) * 3 - 1;
            int yy = y + dy, xx = b_n + dx;
            float v = 0.f;
            if ((unsigned)yy < 128u && (unsigned)xx < 128u)
                v = g_fused[((b * Cc + ci) << 14) + (yy << 7) + xx];
            Bs[0][kb][b_n] = v;
        }
    }
    __syncthreads();

    for (int ch = 0; ch < NCH; ch++) {
        int cur = ch & 1;
        // ---- prefetch next chunk into the other buffer ----
        if (ch + 1 < NCH) {
            int k0 = (ch + 1) * 8;
#pragma unroll
            for (int i = 0; i < 4; i++) {
                int m = a_m + 32 * i;
                int row = m0 + m;
                As[cur ^ 1][a_kk][m] = (row < M2) ? g_Wall[row * KTOT + k0 + a_kk] : 0.f;
            }
#pragma unroll
            for (int i = 0; i < 4; i++) {
                int kb = b_kb + 2 * i;
                int k  = k0 + kb;
                int ci = k / 9;
                int tap = k - ci * 9;
                int dy = tap / 3 - 1;
                int dx = tap - (tap / 3) * 3 - 1;
                int yy = y + dy, xx = b_n + dx;
                float v = 0.f;
                if ((unsigned)yy < 128u && (unsigned)xx < 128u)
                    v = g_fused[((b * Cc + ci) << 14) + (yy << 7) + xx];
                Bs[cur ^ 1][kb][b_n] = v;
            }
        }
        // ---- compute on current buffer ----
#pragma unroll
        for (int j = 0; j < 8; j++) {
            float a[8], bb[8];
            *(float4*)&a[0]  = *(const float4*)&As[cur][j][tm0];
            *(float4*)&a[4]  = *(const float4*)&As[cur][j][tm0 + 64];
            *(float4*)&bb[0] = *(const float4*)&Bs[cur][j][tn0];
            *(float4*)&bb[4] = *(const float4*)&Bs[cur][j][tn0 + 64];
#pragma unroll
            for (int ii = 0; ii < 8; ii++)
#pragma unroll
                for (int jj = 0; jj < 8; jj++)
                    acc[ii][jj] += a[ii] * bb[jj];
        }
        __syncthreads();
    }

    int hwb = (y << 7);
    int bhw = b * HW;
#pragma unroll
    for (int ii2 = 0; ii2 < 2; ii2++)
#pragma unroll
    for (int ii = 0; ii < 4; ii++) {
        int row = m0 + tm0 + ii2 * 64 + ii;
        if (row >= M2) continue;
        float bi = g_Ball[row];
#pragma unroll
        for (int jj2 = 0; jj2 < 2; jj2++)
#pragma unroll
        for (int jj = 0; jj < 4; jj++) {
            float v = acc[ii2 * 4 + ii][jj2 * 4 + jj] + bi;
            int hw = hwb + tn0 + jj2 * 64 + jj;
            if (row < 18)
                g_off[((b * 18 + row) << 14) + hw] = v;
            else if (row < 27)
                g_m[((b * 9 + (row - 18)) << 14) + hw] = fast_sigmoid(v);
            else {
                int t = row - 27;
                int cch = t / 9;
                int nn  = t - cch * 9;
                g_cofft[(size_t)(bhw + hw) * KTOT + nn * 64 + cch] = fast_tanh(v);
            }
        }
    }
}

// ============================================================
// Kernel 3: deformable bilinear sampling + c_off + mask + final conv.
// ============================================================
__global__ __launch_bounds__(256) void sample_final_kernel(float* __restrict__ out)
{
    __shared__ float v_s[16][577];
    __shared__ int   idx_s[16][9][4];
    __shared__ float g_s[16][9][4];
    __shared__ float m_s[16][9];
    __shared__ float Ws[16][64];

    int tid = threadIdx.x;
    int px0 = blockIdx.x * 16;
    int b   = px0 >> 14;
    int rem = px0 & (HW - 1);
    int y   = rem >> 7;
    int x0  = rem & 127;

    if (tid < 144) {
        int px = tid / 9, n = tid - (tid / 9) * 9;
        int xg = x0 + px;
        int hw = (y << 7) + xg;
        float offr = g_off[((b * 18 + n) << 14) + hw];
        float offc = g_off[((b * 18 + 9 + n) << 14) + hw];
        m_s[px][n] = g_m[((b * 9 + n) << 14) + hw];

        float pr = (float)(y + 1 + (n / 3) - 1) + offr;
        float pc = (float)(xg + 1 + (n % 3) - 1) + offc;
        float fr = floorf(pr), fc = floorf(pc);
        int lt_r = min(max((int)fr, 0), 129);
        int rb_r = min(max((int)fr + 1, 0), 129);
        int lt_c = min(max((int)fc, 0), 129);
        int rb_c = min(max((int)fc + 1, 0), 129);
        float prc = fminf(fmaxf(pr, 0.f), 129.f);
        float pcc = fminf(fmaxf(pc, 0.f), 129.f);
        float ar_lt = 1.f + (float)lt_r - prc;
        float ar_rb = 1.f - ((float)rb_r - prc);
        float ac_lt = 1.f + (float)lt_c - pcc;
        float ac_rb = 1.f - ((float)rb_c - pcc);
        g_s[px][n][0] = ar_lt * ac_lt;
        g_s[px][n][1] = ar_rb * ac_rb;
        g_s[px][n][2] = ar_lt * ac_rb;
        g_s[px][n][3] = ar_rb * ac_lt;
        int rl = lt_r - 1, cl = lt_c - 1, rr = rb_r - 1, cr = rb_c - 1;
        idx_s[px][n][0] = ((unsigned)rl < 128u && (unsigned)cl < 128u) ? (rl << 7) + cl : -1;
        idx_s[px][n][1] = ((unsigned)rr < 128u && (unsigned)cr < 128u) ? (rr << 7) + cr : -1;
        idx_s[px][n][2] = ((unsigned)rl < 128u && (unsigned)cr < 128u) ? (rl << 7) + cr : -1;
        idx_s[px][n][3] = ((unsigned)rr < 128u && (unsigned)cl < 128u) ? (rr << 7) + cl : -1;
    }
    __syncthreads();

    {
        int c = tid & 63;
        const float* xtb = g_xt + ((size_t)(b * HW) << 6);
#pragma unroll
        for (int p = 0; p < 4; p++) {
            int px = (tid >> 6) * 4 + p;
            int hw = (y << 7) + x0 + px;
            const float* cofft = g_cofft + (size_t)(b * HW + hw) * KTOT;
#pragma unroll
            for (int n = 0; n < 9; n++) {
                int i0 = idx_s[px][n][0], i1 = idx_s[px][n][1];
                int i2 = idx_s[px][n][2], i3 = idx_s[px][n][3];
                float w0 = g_s[px][n][0], w1 = g_s[px][n][1];
                float w2 = g_s[px][n][2], w3 = g_s[px][n][3];
                float mm = m_s[px][n];
                float s = 0.f;
                if (i0 >= 0) s += w0 * xtb[(i0 << 6) + c];
                if (i1 >= 0) s += w1 * xtb[(i1 << 6) + c];
                if (i2 >= 0) s += w2 * xtb[(i2 << 6) + c];
                if (i3 >= 0) s += w3 * xtb[(i3 << 6) + c];
                float coff = cofft[n * 64 + c];
                v_s[px][c * 9 + n] = (s + coff) * mm;
            }
        }
    }
    __syncthreads();

    int px  = tid & 15;
    int oc0 = (tid >> 4) << 2;
    float acc[4] = {};
    for (int k0 = 0; k0 < KTOT; k0 += 16) {
#pragma unroll
        for (int i = 0; i < 4; i++) {
            int e  = tid + 256 * i;
            int kk = e >> 6, oc = e & 63;
            Ws[kk][oc] = g_wt[(k0 + kk) * 64 + oc];
        }
        __syncthreads();
#pragma unroll
        for (int kk = 0; kk < 16; kk++) {
            float bv = v_s[px][k0 + kk];
            float4 wv = *(const float4*)&Ws[kk][oc0];
            acc[0] += wv.x * bv;
            acc[1] += wv.y * bv;
            acc[2] += wv.z * bv;
            acc[3] += wv.w * bv;
        }
        __syncthreads();
    }
    int hw = (y << 7) + x0 + px;
#pragma unroll
    for (int i = 0; i < 4; i++)
        out[((b * OUTC + oc0 + i) << 14) + hw] = acc[i];
}

// ============================================================
extern "C" void kernel_launch(void* const* d_in, const int* in_sizes, int n_in,
                              void* d_out, int out_size)
{
    const float* x      = (const float*)d_in[0];
    const float* ref    = (const float*)d_in[1];
    const float* w_cd   = (const float*)d_in[2];
    const float* b_cd   = (const float*)d_in[3];
    const float* w_p    = (const float*)d_in[4];
    const float* b_p    = (const float*)d_in[5];
    const float* w_m    = (const float*)d_in[6];
    const float* b_m    = (const float*)d_in[7];
    const float* w_c    = (const float*)d_in[8];
    const float* b_c    = (const float*)d_in[9];
    const float* w_conv = (const float*)d_in[10];
    float* out = (float*)d_out;

    int packN = M2 * KTOT + M2 + OUTC * KTOT;
    pack_kernel<<<(packN + 255) / 256, 256>>>(w_p, w_m, w_c, b_p, b_m, b_c, w_conv);

    dim3 gt(HW / 32, Cc / 32, Bn);
    transpose_kernel<<<gt, dim3(32, 8)>>>(x);

    conv1x1_kernel<<<(Bn * HW) / 64, 256>>>(x, ref, w_cd, b_cd);

    dim3 g2((Bn * HW) / 128, 5);
    conv3x3_kernel<<<g2, 256>>>();

    sample_final_kernel<<<(Bn * HW) / 16, 256>>>(out);
}